// round 2
// baseline (speedup 1.0000x reference)
#include <cuda_runtime.h>

#define TPB 128
#define W   1116

__device__ __forceinline__ float softf(float c, float t) {
    return copysignf(fmaxf(fabsf(c) - t, 0.0f), c);
}

// Shared layout (floats), all bases 16B-aligned:
//  [0..571]      eA (front pad 4 -> data at 4)      \  forward set A
//  [572..1143]   oA (front pad 4 -> data at 576)    /
//  [1144..1439]  eB (front pad 4 -> data at 1148)   \  forward set B
//  [1440..1735]  oB (front pad 4 -> data at 1444)   /
//  [1736..1755]  a7 (final approx, linear, 15 used)
//  [1756..2915]  sD (all detail levels, 4-aligned regions)
//  Inverse aliases: lin0 = sm+0 (<=1120), lin1 = sm+1120 (<=564)
__global__ void __launch_bounds__(TPB) wavelet_kernel(
    const float* __restrict__ x, const float* __restrict__ rawthr,
    float* __restrict__ out)
{
    constexpr float DLO[8] = {
        -0.010597401784997278f,  0.032883011666982945f,
         0.030841381835986965f, -0.18703481171888114f,
        -0.02798376941698385f,   0.6308807679295904f,
         0.7148465705525415f,    0.23037781330885523f };

    constexpr int NS[8]   = {1116, 561, 284, 145, 76, 41, 24, 15};
    constexpr int DOFF[7] = {0, 564, 848, 996, 1072, 1116, 1140};

    __shared__ __align__(16) float sm[2916];
    float* const EP[2] = { sm + 4,   sm + 1148 };
    float* const OP[2] = { sm + 576, sm + 1444 };
    float* const a7 = sm + 1736;
    float* const sD = sm + 1756;

    const int tid = threadIdx.x;
    const long row = blockIdx.x;
    const float thr = fmaxf(rawthr[0], 0.01f);

    // ---- Stage input row, de-interleaved into e/o arrays ----
    {
        const float4* xin = (const float4*)(x + row * W);
        float* e = EP[0]; float* o = OP[0];
        for (int i = tid; i < W / 4; i += TPB) {
            float4 v = xin[i];
            ((float2*)e)[i] = make_float2(v.x, v.z);
            ((float2*)o)[i] = make_float2(v.y, v.w);
        }
        // front pads of all 4 arrays + tail pads of input arrays
        if (tid < 4) { sm[tid] = 0.f; sm[572 + tid] = 0.f; sm[1144 + tid] = 0.f; sm[1440 + tid] = 0.f; }
        if (tid < 8) { e[558 + tid] = 0.f; o[558 + tid] = 0.f; }
    }
    __syncthreads();

    // ---- Forward: 7 DWT levels on de-interleaved data ----
    #pragma unroll
    for (int l = 0; l < 7; l++) {
        const int nout = NS[l + 1];
        const float* se = EP[l & 1];
        const float* so = OP[l & 1];
        float* de  = EP[(l + 1) & 1];
        float* do_ = OP[(l + 1) & 1];
        float* dd  = sD + DOFF[l];
        const int groups = (nout + 3) >> 2;

        for (int g = tid; g < groups; g += TPB) {
            // conflict-free LDS.128: lane stride 16B
            float4 E0 = *(const float4*)(se + 4 * g - 4);
            float4 E1 = *(const float4*)(se + 4 * g);
            float4 O0 = *(const float4*)(so + 4 * g - 4);
            float4 O1 = *(const float4*)(so + 4 * g);
            float we[8] = {E0.x, E0.y, E0.z, E0.w, E1.x, E1.y, E1.z, E1.w};
            float wo[8] = {O0.x, O0.y, O0.z, O0.w, O1.x, O1.y, O1.z, O1.w};

            float ca[4], cd[4];
            #pragma unroll
            for (int k = 0; k < 4; k++) {
                float a = 0.f, d = 0.f;
                #pragma unroll
                for (int m = 0; m < 4; m++) {
                    float ev = we[k + 4 - m], ov = wo[k + 4 - m];
                    a = fmaf(DLO[2 * m + 1],  ev, a);   // dec_lo odd taps -> even samples
                    a = fmaf(DLO[2 * m],      ov, a);   // dec_lo even taps -> odd samples
                    d = fmaf(DLO[6 - 2 * m],  ev, d);   // dec_hi odd taps
                    d = fmaf(-DLO[7 - 2 * m], ov, d);   // dec_hi even taps
                }
                ca[k] = a;
                cd[k] = softf(d, thr);
            }

            if (4 * g + 3 < nout) {  // full group
                *(float4*)(dd + 4 * g) = make_float4(cd[0], cd[1], cd[2], cd[3]);
                if (l < 6) {
                    *(float2*)(de  + 2 * g) = make_float2(ca[0], ca[2]);
                    *(float2*)(do_ + 2 * g) = make_float2(ca[1], ca[3]);
                } else {
                    *(float4*)(a7 + 4 * g) = make_float4(
                        softf(ca[0], thr), softf(ca[1], thr),
                        softf(ca[2], thr), softf(ca[3], thr));
                }
            } else {                 // guarded tail group
                #pragma unroll
                for (int k = 0; k < 4; k++) {
                    int i = 4 * g + k;
                    if (i < nout) {
                        dd[i] = cd[k];
                        if (l < 6) {
                            if (i & 1) do_[i >> 1] = ca[k];
                            else       de[i >> 1]  = ca[k];
                        } else {
                            a7[i] = softf(ca[k], thr);
                        }
                    }
                }
            }
        }
        // zero tail pads of the destination arrays (disjoint from guarded writes)
        if (l < 6 && tid < 8) {
            const int ec = (nout + 1) >> 1, oc = nout >> 1;
            de[ec + tid]  = 0.f;
            do_[oc + tid] = 0.f;
        }
        __syncthreads();
    }

    // ---- Inverse: 7 IDWT levels on linear buffers (alias forward region) ----
    float* const lin0 = sm;
    float* const lin1 = sm + 1120;

    #pragma unroll
    for (int s = 6; s >= 0; s--) {
        const int n = NS[s + 1];                     // detail length (truncation implicit)
        const float* a = (s == 6) ? a7 : ((((5 - s) & 1)) ? lin1 : lin0);
        float* dst     = (((6 - s) & 1)) ? lin1 : lin0;
        const float* d = sD + DOFF[s];
        const int pairs  = n - 3;
        const int groups = (pairs + 1) >> 1;

        for (int g = tid; g < groups; g += TPB) {
            float2 A0 = *(const float2*)(a + 2 * g);
            float2 A1 = *(const float2*)(a + 2 * g + 2);
            float2 A2 = *(const float2*)(a + 2 * g + 4);
            float2 D0 = *(const float2*)(d + 2 * g);
            float2 D1 = *(const float2*)(d + 2 * g + 2);
            float2 D2 = *(const float2*)(d + 2 * g + 4);
            float wa[5] = {A0.x, A0.y, A1.x, A1.y, A2.x};
            float wd[5] = {D0.x, D0.y, D1.x, D1.y, D2.x};

            float ye0 = 0.f, yo0 = 0.f, ye1 = 0.f, yo1 = 0.f;
            #pragma unroll
            for (int q = 0; q < 4; q++) {
                ye0 = fmaf(DLO[7 - 2 * q],  wa[3 - q], ye0);
                ye0 = fmaf(DLO[2 * q],      wd[3 - q], ye0);
                yo0 = fmaf(DLO[6 - 2 * q],  wa[3 - q], yo0);
                yo0 = fmaf(-DLO[2 * q + 1], wd[3 - q], yo0);
                ye1 = fmaf(DLO[7 - 2 * q],  wa[4 - q], ye1);
                ye1 = fmaf(DLO[2 * q],      wd[4 - q], ye1);
                yo1 = fmaf(DLO[6 - 2 * q],  wa[4 - q], yo1);
                yo1 = fmaf(-DLO[2 * q + 1], wd[4 - q], yo1);
            }

            if (2 * g + 1 < pairs) {
                *(float4*)(dst + 4 * g) = make_float4(ye0, yo0, ye1, yo1);
            } else {
                *(float2*)(dst + 4 * g) = make_float2(ye0, yo0);
            }
        }
        __syncthreads();
    }

    // ---- Store final result (lin0, length 1116) ----
    float4* o = (float4*)(out + row * W);
    for (int i = tid; i < W / 4; i += TPB)
        o[i] = ((const float4*)lin0)[i];
}

extern "C" void kernel_launch(void* const* d_in, const int* in_sizes, int n_in,
                              void* d_out, int out_size) {
    const float* x   = (const float*)d_in[0];
    const float* thr = (const float*)d_in[1];
    float* out = (float*)d_out;
    const int rows = in_sizes[0] / W;
    wavelet_kernel<<<rows, TPB>>>(x, thr, out);
}

// round 5
// speedup vs baseline: 1.6058x; 1.6058x over previous
#include <cuda_runtime.h>

#define TPB 128
#define W   1116

__device__ __forceinline__ float softf(float c, float t) {
    return copysignf(fmaxf(fabsf(c) - t, 0.0f), c);
}

// Shared layout (floats), all bases 16B-aligned:
//  [0..571]      eA (front pad 4 -> data at 4)      \  forward set A
//  [572..1143]   oA (front pad 4 -> data at 576)    /
//  [1144..1439]  eB (front pad 4 -> data at 1148)   \  forward set B
//  [1440..1735]  oB (front pad 4 -> data at 1444)   /
//  [1736..1755]  a7 (final approx, linear, 15 used)
//  [1756..2915]  sD (all detail levels, 4-aligned regions)
//  Inverse aliases: lin0 = sm+0 (<=1120), lin1 = sm+1120 (<=564)
__global__ void __launch_bounds__(TPB, 8) wavelet_kernel(
    const float* __restrict__ x, const float* __restrict__ rawthr,
    float* __restrict__ out)
{
    constexpr float DLO[8] = {
        -0.010597401784997278f,  0.032883011666982945f,
         0.030841381835986965f, -0.18703481171888114f,
        -0.02798376941698385f,   0.6308807679295904f,
         0.7148465705525415f,    0.23037781330885523f };

    constexpr int NS[8]   = {1116, 561, 284, 145, 76, 41, 24, 15};
    constexpr int DOFF[7] = {0, 564, 848, 996, 1072, 1116, 1140};

    __shared__ __align__(16) float sm[2916];
    float* const EP[2] = { sm + 4,   sm + 1148 };
    float* const OP[2] = { sm + 576, sm + 1444 };
    float* const a7 = sm + 1736;
    float* const sD = sm + 1756;

    const int tid = threadIdx.x;
    const long row = blockIdx.x;
    const float thr = fmaxf(rawthr[0], 0.01f);

    // ---- Stage input row, de-interleaved into e/o arrays ----
    {
        const float4* xin = (const float4*)(x + row * W);
        float* e = EP[0]; float* o = OP[0];
        for (int i = tid; i < W / 4; i += TPB) {
            float4 v = xin[i];
            ((float2*)e)[i] = make_float2(v.x, v.z);
            ((float2*)o)[i] = make_float2(v.y, v.w);
        }
        // front pads of all 4 arrays + tail pads of input arrays
        if (tid < 4) { sm[tid] = 0.f; sm[572 + tid] = 0.f; sm[1144 + tid] = 0.f; sm[1440 + tid] = 0.f; }
        if (tid < 8) { e[558 + tid] = 0.f; o[558 + tid] = 0.f; }
    }
    __syncthreads();

    // ---- Forward: 7 DWT levels on de-interleaved data ----
    #pragma unroll
    for (int l = 0; l < 7; l++) {
        const int nout = NS[l + 1];
        const float* se = EP[l & 1];
        const float* so = OP[l & 1];
        float* de  = EP[(l + 1) & 1];
        float* do_ = OP[(l + 1) & 1];
        float* dd  = sD + DOFF[l];
        const int groups = (nout + 3) >> 2;

        for (int g = tid; g < groups; g += TPB) {
            // conflict-free LDS.128 windows
            float4 E0 = *(const float4*)(se + 4 * g - 4);
            float4 E1 = *(const float4*)(se + 4 * g);
            float4 O0 = *(const float4*)(so + 4 * g - 4);
            float4 O1 = *(const float4*)(so + 4 * g);
            float we[8] = {E0.x, E0.y, E0.z, E0.w, E1.x, E1.y, E1.z, E1.w};
            float wo[8] = {O0.x, O0.y, O0.z, O0.w, O1.x, O1.y, O1.z, O1.w};

            float ca[4], cd[4];
            #pragma unroll
            for (int k = 0; k < 4; k++) {
                float a = 0.f, d = 0.f;
                #pragma unroll
                for (int m = 0; m < 4; m++) {
                    float ev = we[k + 4 - m], ov = wo[k + 4 - m];
                    a = fmaf(DLO[2 * m + 1],  ev, a);   // dec_lo odd taps -> even samples
                    a = fmaf(DLO[2 * m],      ov, a);   // dec_lo even taps -> odd samples
                    d = fmaf(DLO[6 - 2 * m],  ev, d);   // dec_hi odd taps
                    d = fmaf(-DLO[7 - 2 * m], ov, d);   // dec_hi even taps
                }
                ca[k] = a;
                cd[k] = softf(d, thr);
            }

            if (4 * g + 3 < nout) {  // full group
                *(float4*)(dd + 4 * g) = make_float4(cd[0], cd[1], cd[2], cd[3]);
                if (l < 6) {
                    *(float2*)(de  + 2 * g) = make_float2(ca[0], ca[2]);
                    *(float2*)(do_ + 2 * g) = make_float2(ca[1], ca[3]);
                } else {
                    *(float4*)(a7 + 4 * g) = make_float4(
                        softf(ca[0], thr), softf(ca[1], thr),
                        softf(ca[2], thr), softf(ca[3], thr));
                }
            } else {                 // guarded tail group
                #pragma unroll
                for (int k = 0; k < 4; k++) {
                    int i = 4 * g + k;
                    if (i < nout) {
                        dd[i] = cd[k];
                        if (l < 6) {
                            if (i & 1) do_[i >> 1] = ca[k];
                            else       de[i >> 1]  = ca[k];
                        } else {
                            a7[i] = softf(ca[k], thr);
                        }
                    }
                }
            }
        }
        // zero tail pads of the destination arrays (disjoint from guarded writes)
        if (l < 6 && tid < 8) {
            const int ec = (nout + 1) >> 1, oc = nout >> 1;
            de[ec + tid]  = 0.f;
            do_[oc + tid] = 0.f;
        }
        __syncthreads();
    }

    // ---- Inverse: 7 IDWT levels on linear buffers (alias forward region) ----
    float* const lin0 = sm;
    float* const lin1 = sm + 1120;

    #pragma unroll
    for (int s = 6; s >= 0; s--) {
        const int n = NS[s + 1];                     // detail length (truncation implicit)
        const float* a = (s == 6) ? a7 : ((((5 - s) & 1)) ? lin1 : lin0);
        float* dst     = (((6 - s) & 1)) ? lin1 : lin0;
        const float* d = sD + DOFF[s];
        const int pairs  = n - 3;
        const int groups = (pairs + 1) >> 1;

        for (int g = tid; g < groups; g += TPB) {
            float2 A0 = *(const float2*)(a + 2 * g);
            float2 A1 = *(const float2*)(a + 2 * g + 2);
            float2 A2 = *(const float2*)(a + 2 * g + 4);
            float2 D0 = *(const float2*)(d + 2 * g);
            float2 D1 = *(const float2*)(d + 2 * g + 2);
            float2 D2 = *(const float2*)(d + 2 * g + 4);
            float wa[5] = {A0.x, A0.y, A1.x, A1.y, A2.x};
            float wd[5] = {D0.x, D0.y, D1.x, D1.y, D2.x};

            float ye0 = 0.f, yo0 = 0.f, ye1 = 0.f, yo1 = 0.f;
            #pragma unroll
            for (int q = 0; q < 4; q++) {
                ye0 = fmaf(DLO[7 - 2 * q],  wa[3 - q], ye0);
                ye0 = fmaf(DLO[2 * q],      wd[3 - q], ye0);
                yo0 = fmaf(DLO[6 - 2 * q],  wa[3 - q], yo0);
                yo0 = fmaf(-DLO[2 * q + 1], wd[3 - q], yo0);
                ye1 = fmaf(DLO[7 - 2 * q],  wa[4 - q], ye1);
                ye1 = fmaf(DLO[2 * q],      wd[4 - q], ye1);
                yo1 = fmaf(DLO[6 - 2 * q],  wa[4 - q], yo1);
                yo1 = fmaf(-DLO[2 * q + 1], wd[4 - q], yo1);
            }

            if (2 * g + 1 < pairs) {
                *(float4*)(dst + 4 * g) = make_float4(ye0, yo0, ye1, yo1);
            } else {
                *(float2*)(dst + 4 * g) = make_float2(ye0, yo0);
            }
        }
        __syncthreads();
    }

    // ---- Store final result (lin0, length 1116) ----
    float4* o = (float4*)(out + row * W);
    for (int i = tid; i < W / 4; i += TPB)
        o[i] = ((const float4*)lin0)[i];
}

extern "C" void kernel_launch(void* const* d_in, const int* in_sizes, int n_in,
                              void* d_out, int out_size) {
    const float* x   = (const float*)d_in[0];
    const float* thr = (const float*)d_in[1];
    float* out = (float*)d_out;
    const int rows = in_sizes[0] / W;
    wavelet_kernel<<<rows, TPB>>>(x, thr, out);
}